// round 2
// baseline (speedup 1.0000x reference)
#include <cuda_runtime.h>
#include <math.h>

// Problem shapes (fixed for this problem instance)
#define S_LEN 1024
#define HEADS 8
#define DH    64
#define BM    64     // query tile
#define BN    64     // key tile
#define PAD   65     // smem row pad (floats)

// Bias lookup tables
#define NTAB   2048
#define TAB_LO (-0.5f)
#define TAB_HI (10.5f)

// Device-global scratch for the two bias tables: [0]=distance, [1]=energy.
// Each entry: (f_i, f_{i+1}-f_i) for one-load lerp.
__device__ float2 g_tab[2][NTAB];

__device__ __forceinline__ float gelu_exact(float x) {
    return 0.5f * x * (1.0f + erff(x * 0.70710678118654752f));
}

// ---------------------------------------------------------------------------
// Kernel 1: build the two scalar-bias tables. f(x) = W2 @ gelu(W1 @ psi(x) + b1) + b2
// Cost is negligible (4096 threads); use accurate expf/erff here.
// ---------------------------------------------------------------------------
__global__ void build_tables_kernel(
    const float* __restrict__ muD, const float* __restrict__ sgD, const float* __restrict__ bD,
    const float* __restrict__ muE, const float* __restrict__ sgE, const float* __restrict__ bE,
    const float* __restrict__ W1,  const float* __restrict__ b1,
    const float* __restrict__ W2,  const float* __restrict__ b2,
    int KG)
{
    int t     = blockIdx.x * blockDim.x + threadIdx.x;   // 0..NTAB-1
    int which = blockIdx.y;                               // 0 = D, 1 = E
    if (t >= NTAB) return;

    const float* mu = which ? muE : muD;
    const float* sg = which ? sgE : sgD;
    const float* bb = which ? bE  : bD;

    const float step = (TAB_HI - TAB_LO) / (float)NTAB;

    float f[2];
    #pragma unroll
    for (int p = 0; p < 2; ++p) {
        float x = TAB_LO + (float)(t + p) * step;
        float psi[16];
        for (int k = 0; k < KG; ++k) {
            float s  = sg[k];
            float z  = (x + bb[k] - mu[k]) / s;
            float in = 0.3989422804014327f / s;   // 1/(sqrt(2*pi)*sigma)
            psi[k]   = expf(-0.5f * z * z) * in;
        }
        float hv[16];
        for (int l = 0; l < KG; ++l) {
            float acc = b1[l];
            for (int k = 0; k < KG; ++k) acc += psi[k] * W1[l * KG + k];
            hv[l] = gelu_exact(acc);
        }
        float o = b2[0];
        for (int l = 0; l < KG; ++l) o += hv[l] * W2[l];
        f[p] = o;
    }
    g_tab[which][t] = make_float2(f[0], f[1] - f[0]);
}

// ---------------------------------------------------------------------------
// Kernel 2: fused flash attention with table-based biases.
// Grid: (S/BM, HEADS). Block: 256 threads = 16x16, each owns a 4x4 of the
// 64x64 score tile and a 4x4 of the 64x64 output tile.
// ---------------------------------------------------------------------------
__global__ void __launch_bounds__(256, 1)
attn_kernel(const float* __restrict__ Q, const float* __restrict__ K,
            const float* __restrict__ V,
            const float* __restrict__ dist, const float* __restrict__ ener,
            const int*   __restrict__ mask,
            float* __restrict__ out)
{
    extern __shared__ float smem[];
    float*  Qs = smem;                       // BM x PAD
    float*  Ks = Qs + BM * PAD;              // BN x PAD (reused as P tile)
    float*  Vs = Ks + BN * PAD;              // BN x PAD
    float2* tD = (float2*)(Vs + BN * PAD);   // NTAB
    float2* tE = tD + NTAB;                  // NTAB

    const int tid = threadIdx.x;
    const int tx  = tid & 15;
    const int ty  = tid >> 4;
    const int h   = blockIdx.y;
    const int q0  = blockIdx.x * BM;
    const int r0  = ty * 4;
    const int c0  = tx * 4;

    // ---- stage tables into smem ----
    for (int i = tid; i < NTAB; i += 256) {
        tD[i] = g_tab[0][i];
        tE[i] = g_tab[1][i];
    }

    // ---- stage Q tile (pre-scaled by 1/sqrt(2*D)) ----
    const float SCALE = 0.08838834764831845f;   // 1/sqrt(128)
    const float* Qg = Q + ((size_t)h * S_LEN + q0) * DH;
    for (int i = tid; i < BM * (DH / 4); i += 256) {
        int r  = i >> 4;
        int c4 = (i & 15) << 2;
        float4 v = *(const float4*)(Qg + r * DH + c4);
        float* dst = Qs + r * PAD + c4;
        dst[0] = v.x * SCALE; dst[1] = v.y * SCALE;
        dst[2] = v.z * SCALE; dst[3] = v.w * SCALE;
    }

    float m[4], l[4], o[4][4];
    #pragma unroll
    for (int i = 0; i < 4; ++i) {
        m[i] = -1e30f; l[i] = 0.f;
        #pragma unroll
        for (int j = 0; j < 4; ++j) o[i][j] = 0.f;
    }

    const float inv_step = (float)NTAB / (TAB_HI - TAB_LO);

    for (int jt = 0; jt < S_LEN / BN; ++jt) {
        __syncthreads();   // covers table/Q staging (iter 0) and prior PV reads
        // ---- stage K, V tiles ----
        const float* Kg = K + ((size_t)h * S_LEN + jt * BN) * DH;
        const float* Vg = V + ((size_t)h * S_LEN + jt * BN) * DH;
        for (int i = tid; i < BN * (DH / 4); i += 256) {
            int r  = i >> 4;
            int c4 = (i & 15) << 2;
            float4 kv = *(const float4*)(Kg + r * DH + c4);
            float* kd = Ks + r * PAD + c4;
            kd[0] = kv.x; kd[1] = kv.y; kd[2] = kv.z; kd[3] = kv.w;
            float4 vv = *(const float4*)(Vg + r * DH + c4);
            float* vd = Vs + r * PAD + c4;
            vd[0] = vv.x; vd[1] = vv.y; vd[2] = vv.z; vd[3] = vv.w;
        }
        __syncthreads();

        // ---- S = Qs @ Ks^T (4x4 per thread) ----
        float s[4][4];
        #pragma unroll
        for (int i = 0; i < 4; ++i)
            #pragma unroll
            for (int j = 0; j < 4; ++j) s[i][j] = 0.f;

        #pragma unroll 8
        for (int k = 0; k < DH; ++k) {
            float a0 = Qs[(r0 + 0) * PAD + k];
            float a1 = Qs[(r0 + 1) * PAD + k];
            float a2 = Qs[(r0 + 2) * PAD + k];
            float a3 = Qs[(r0 + 3) * PAD + k];
            float b0 = Ks[(c0 + 0) * PAD + k];
            float b1v = Ks[(c0 + 1) * PAD + k];
            float b2v = Ks[(c0 + 2) * PAD + k];
            float b3 = Ks[(c0 + 3) * PAD + k];
            s[0][0] += a0 * b0;  s[0][1] += a0 * b1v; s[0][2] += a0 * b2v; s[0][3] += a0 * b3;
            s[1][0] += a1 * b0;  s[1][1] += a1 * b1v; s[1][2] += a1 * b2v; s[1][3] += a1 * b3;
            s[2][0] += a2 * b0;  s[2][1] += a2 * b1v; s[2][2] += a2 * b2v; s[2][3] += a2 * b3;
            s[3][0] += a3 * b0;  s[3][1] += a3 * b1v; s[3][2] += a3 * b2v; s[3][3] += a3 * b3;
        }

        // ---- add table biases + mask (streamed from gmem, used once) ----
        #pragma unroll
        for (int i = 0; i < 4; ++i) {
            size_t rowbase = ((size_t)h * S_LEN + (q0 + r0 + i)) * S_LEN
                             + (size_t)(jt * BN + c0);
            float4 dd = *(const float4*)(dist + rowbase);
            float4 ee = *(const float4*)(ener + rowbase);
            int4   mm = *(const int4*)(mask + rowbase);
            float dv[4] = {dd.x, dd.y, dd.z, dd.w};
            float ev[4] = {ee.x, ee.y, ee.z, ee.w};
            int   mv[4] = {mm.x, mm.y, mm.z, mm.w};
            #pragma unroll
            for (int j = 0; j < 4; ++j) {
                float t  = (dv[j] - TAB_LO) * inv_step;
                int   ix = (int)t;
                ix = min(max(ix, 0), NTAB - 1);
                float fr = t - (float)ix;
                float2 eD = tD[ix];
                float bias = eD.x + fr * eD.y;

                t  = (ev[j] - TAB_LO) * inv_step;
                ix = (int)t;
                ix = min(max(ix, 0), NTAB - 1);
                fr = t - (float)ix;
                float2 eE = tE[ix];
                bias += eE.x + fr * eE.y;

                float sv = s[i][j] + bias;
                s[i][j] = (mv[j] == 0) ? -1e9f : sv;
            }
        }

        // ---- online softmax (row stats reduced over the 16-lane tx group) ----
        float corr[4];
        #pragma unroll
        for (int i = 0; i < 4; ++i) {
            float rm = fmaxf(fmaxf(s[i][0], s[i][1]), fmaxf(s[i][2], s[i][3]));
            rm = fmaxf(rm, __shfl_xor_sync(0xffffffffu, rm, 1));
            rm = fmaxf(rm, __shfl_xor_sync(0xffffffffu, rm, 2));
            rm = fmaxf(rm, __shfl_xor_sync(0xffffffffu, rm, 4));
            rm = fmaxf(rm, __shfl_xor_sync(0xffffffffu, rm, 8));
            float mn = fmaxf(m[i], rm);
            corr[i]  = __expf(m[i] - mn);
            m[i]     = mn;
            float rs = 0.f;
            #pragma unroll
            for (int j = 0; j < 4; ++j) {
                float p = __expf(s[i][j] - mn);
                s[i][j] = p;
                rs += p;
            }
            rs += __shfl_xor_sync(0xffffffffu, rs, 1);
            rs += __shfl_xor_sync(0xffffffffu, rs, 2);
            rs += __shfl_xor_sync(0xffffffffu, rs, 4);
            rs += __shfl_xor_sync(0xffffffffu, rs, 8);
            l[i] = l[i] * corr[i] + rs;
            #pragma unroll
            for (int j = 0; j < 4; ++j) o[i][j] *= corr[i];
        }

        // ---- write P into smem (reuse Ks buffer) ----
        __syncthreads();   // everyone done reading Ks
        #pragma unroll
        for (int i = 0; i < 4; ++i)
            #pragma unroll
            for (int j = 0; j < 4; ++j)
                Ks[(r0 + i) * PAD + (c0 + j)] = s[i][j];
        __syncthreads();

        // ---- O += P @ V ----
        #pragma unroll 8
        for (int j = 0; j < BN; ++j) {
            float a0 = Ks[(r0 + 0) * PAD + j];
            float a1 = Ks[(r0 + 1) * PAD + j];
            float a2 = Ks[(r0 + 2) * PAD + j];
            float a3 = Ks[(r0 + 3) * PAD + j];
            float b0 = Vs[j * PAD + c0 + 0];
            float b1v = Vs[j * PAD + c0 + 1];
            float b2v = Vs[j * PAD + c0 + 2];
            float b3 = Vs[j * PAD + c0 + 3];
            o[0][0] += a0 * b0;  o[0][1] += a0 * b1v; o[0][2] += a0 * b2v; o[0][3] += a0 * b3;
            o[1][0] += a1 * b0;  o[1][1] += a1 * b1v; o[1][2] += a1 * b2v; o[1][3] += a1 * b3;
            o[2][0] += a2 * b0;  o[2][1] += a2 * b1v; o[2][2] += a2 * b2v; o[2][3] += a2 * b3;
            o[3][0] += a3 * b0;  o[3][1] += a3 * b1v; o[3][2] += a3 * b2v; o[3][3] += a3 * b3;
        }
    }

    // ---- epilogue: normalize + store ----
    #pragma unroll
    for (int i = 0; i < 4; ++i) {
        float invl = 1.0f / l[i];
        float4 res = make_float4(o[i][0] * invl, o[i][1] * invl,
                                 o[i][2] * invl, o[i][3] * invl);
        *(float4*)(out + ((size_t)h * S_LEN + (q0 + r0 + i)) * DH + c0) = res;
    }
}

// ---------------------------------------------------------------------------
// Launch
// ---------------------------------------------------------------------------
extern "C" void kernel_launch(void* const* d_in, const int* in_sizes, int n_in,
                              void* d_out, int out_size)
{
    const float* Q    = (const float*)d_in[0];
    const float* K    = (const float*)d_in[1];
    const float* V    = (const float*)d_in[2];
    const float* dist = (const float*)d_in[3];
    const float* ener = (const float*)d_in[4];
    const int*   mask = (const int*)  d_in[5];
    const float* muD  = (const float*)d_in[6];
    const float* sgD  = (const float*)d_in[7];
    const float* bD   = (const float*)d_in[8];
    const float* muE  = (const float*)d_in[9];
    const float* sgE  = (const float*)d_in[10];
    const float* bE   = (const float*)d_in[11];
    const float* W1   = (const float*)d_in[12];
    const float* b1   = (const float*)d_in[13];
    const float* W2   = (const float*)d_in[14];
    const float* b2   = (const float*)d_in[15];
    float* out = (float*)d_out;

    int KG = in_sizes[6];
    if (KG > 16) KG = 16;

    build_tables_kernel<<<dim3(NTAB / 256, 2), 256>>>(
        muD, sgD, bD, muE, sgE, bE, W1, b1, W2, b2, KG);

    const int SMEM_BYTES = (3 * BM * PAD) * (int)sizeof(float)
                         + 2 * NTAB * (int)sizeof(float2);
    cudaFuncSetAttribute(attn_kernel,
                         cudaFuncAttributeMaxDynamicSharedMemorySize, SMEM_BYTES);

    attn_kernel<<<dim3(S_LEN / BM, HEADS), 256, SMEM_BYTES>>>(
        Q, K, V, dist, ener, mask, out);
}

// round 4
// speedup vs baseline: 1.4446x; 1.4446x over previous
#include <cuda_runtime.h>
#include <math.h>
#include <stdint.h>

// Problem shapes (fixed)
#define S_LEN 1024
#define HEADS 8
#define DH    64
#define BM    64
#define BN    64
#define KSTR  68   // Ks smem row stride (floats): conflict-free for (4g+q) pattern
#define VSTR  72   // Vs smem row stride (floats): conflict-free for (8q+g) pattern

// Bias lookup tables
#define NTAB   2048
#define TAB_LO (-0.5f)
#define TAB_HI (10.5f)

__device__ float2 g_tab[2][NTAB];

__device__ __forceinline__ float gelu_exact(float x) {
    return 0.5f * x * (1.0f + erff(x * 0.70710678118654752f));
}

// ---------------------------------------------------------------------------
// Kernel 1: build the two scalar-bias tables (negligible cost, accurate math)
// ---------------------------------------------------------------------------
__global__ void build_tables_kernel(
    const float* __restrict__ muD, const float* __restrict__ sgD, const float* __restrict__ bD,
    const float* __restrict__ muE, const float* __restrict__ sgE, const float* __restrict__ bE,
    const float* __restrict__ W1,  const float* __restrict__ b1,
    const float* __restrict__ W2,  const float* __restrict__ b2,
    int KG)
{
    int t     = blockIdx.x * blockDim.x + threadIdx.x;
    int which = blockIdx.y;
    if (t >= NTAB) return;

    const float* mu = which ? muE : muD;
    const float* sg = which ? sgE : sgD;
    const float* bb = which ? bE  : bD;

    const float step = (TAB_HI - TAB_LO) / (float)NTAB;

    float f[2];
    #pragma unroll
    for (int p = 0; p < 2; ++p) {
        float x = TAB_LO + (float)(t + p) * step;
        float psi[16];
        for (int k = 0; k < KG; ++k) {
            float s  = sg[k];
            float z  = (x + bb[k] - mu[k]) / s;
            float in = 0.3989422804014327f / s;
            psi[k]   = expf(-0.5f * z * z) * in;
        }
        float hv[16];
        for (int l = 0; l < KG; ++l) {
            float acc = b1[l];
            for (int k = 0; k < KG; ++k) acc += psi[k] * W1[l * KG + k];
            hv[l] = gelu_exact(acc);
        }
        float o = b2[0];
        for (int l = 0; l < KG; ++l) o += hv[l] * W2[l];
        f[p] = o;
    }
    g_tab[which][t] = make_float2(f[0], f[1] - f[0]);
}

// ---------------------------------------------------------------------------
// tf32 helpers
// ---------------------------------------------------------------------------
__device__ __forceinline__ uint32_t f2tf(float x) {
    uint32_t u;
    asm("cvt.rna.tf32.f32 %0, %1;" : "=r"(u) : "f"(x));
    return u;
}

__device__ __forceinline__ void mma_tf32(
    float& c0, float& c1, float& c2, float& c3,
    uint32_t a0, uint32_t a1, uint32_t a2, uint32_t a3,
    uint32_t b0, uint32_t b1)
{
    asm volatile(
        "mma.sync.aligned.m16n8k8.row.col.f32.tf32.tf32.f32 "
        "{%0,%1,%2,%3}, {%4,%5,%6,%7}, {%8,%9}, {%0,%1,%2,%3};"
        : "+f"(c0), "+f"(c1), "+f"(c2), "+f"(c3)
        : "r"(a0), "r"(a1), "r"(a2), "r"(a3), "r"(b0), "r"(b1));
}

__device__ __forceinline__ float lut(const float2* __restrict__ t, float x, float inv_step) {
    float tt = (x - TAB_LO) * inv_step;
    int ix = (int)tt;
    ix = min(max(ix, 0), NTAB - 1);
    float fr = tt - (float)ix;
    float2 e = t[ix];
    return fmaf(fr, e.y, e.x);
}

// ---------------------------------------------------------------------------
// Kernel 2: fused flash attention, tf32 tensor cores + table biases.
// Grid (16, 8), 256 threads = 8 warps: 4 m-stripes (16 rows) x 2 key-halves.
// ---------------------------------------------------------------------------
__global__ void __launch_bounds__(256, 1)
attn_kernel(const float* __restrict__ Q, const float* __restrict__ K,
            const float* __restrict__ V,
            const float* __restrict__ dist, const float* __restrict__ ener,
            const int*   __restrict__ mask,
            float* __restrict__ out)
{
    extern __shared__ float sm[];
    float*  Ks   = sm;                       // 64 x KSTR (reused as Obuf in epilogue)
    float*  Vs   = Ks + 64 * KSTR;           // 64 x VSTR
    float*  Mred = Vs + 64 * VSTR;           // [2][64] per-half row maxes
    float*  Lred = Mred + 128;               // [2][64] per-half row sums (epilogue)
    float2* tD   = (float2*)(Lred + 128);    // NTAB
    float2* tE   = tD + NTAB;                // NTAB

    const int tid  = threadIdx.x;
    const int w    = tid >> 5;
    const int lane = tid & 31;
    const int g    = lane >> 2;
    const int qd   = lane & 3;
    const int mw   = w >> 1;
    const int half = w & 1;
    const int r_lo = mw * 16 + g;
    const int r_hi = r_lo + 8;
    const int nbase = half * 32;
    const int h    = blockIdx.y;
    const int q0   = blockIdx.x * BM;

    // ---- stage tables ----
    for (int i = tid; i < NTAB; i += 256) {
        tD[i] = g_tab[0][i];
        tE[i] = g_tab[1][i];
    }

    // ---- Q fragments -> registers (tf32-rounded, pre-scaled) ----
    const float SCALE = 0.08838834764831845f;   // 1/sqrt(2*D)
    const float* Qg = Q + ((size_t)h * S_LEN + q0) * DH;
    uint32_t qf[8][4];
    #pragma unroll
    for (int kf = 0; kf < 8; ++kf) {
        int k0 = kf * 8;
        qf[kf][0] = f2tf(Qg[r_lo * DH + k0 + qd]     * SCALE);
        qf[kf][1] = f2tf(Qg[r_hi * DH + k0 + qd]     * SCALE);
        qf[kf][2] = f2tf(Qg[r_lo * DH + k0 + qd + 4] * SCALE);
        qf[kf][3] = f2tf(Qg[r_hi * DH + k0 + qd + 4] * SCALE);
    }

    float o[8][4];
    #pragma unroll
    for (int j = 0; j < 8; ++j)
        #pragma unroll
        for (int c = 0; c < 4; ++c) o[j][c] = 0.f;

    float m_lo = -1e30f, m_hi = -1e30f, l_lo = 0.f, l_hi = 0.f;
    const float inv_step = (float)NTAB / (TAB_HI - TAB_LO);

    for (int jt = 0; jt < S_LEN / BN; ++jt) {
        __syncthreads();   // protect Ks/Vs reuse + table staging (iter 0)

        // ---- stage K, V (tf32-rounded) ----
        const float* Kg = K + ((size_t)h * S_LEN + jt * BN) * DH;
        const float* Vg = V + ((size_t)h * S_LEN + jt * BN) * DH;
        for (int i = tid; i < 1024; i += 256) {     // 64*64/4 float4s
            int r  = i >> 4;
            int c4 = (i & 15) << 2;
            float4 kv = *(const float4*)(Kg + r * DH + c4);
            float4 ck;
            ck.x = __uint_as_float(f2tf(kv.x)); ck.y = __uint_as_float(f2tf(kv.y));
            ck.z = __uint_as_float(f2tf(kv.z)); ck.w = __uint_as_float(f2tf(kv.w));
            *(float4*)&Ks[r * KSTR + c4] = ck;
            float4 vv = *(const float4*)(Vg + r * DH + c4);
            float4 cv;
            cv.x = __uint_as_float(f2tf(vv.x)); cv.y = __uint_as_float(f2tf(vv.y));
            cv.z = __uint_as_float(f2tf(vv.z)); cv.w = __uint_as_float(f2tf(vv.w));
            *(float4*)&Vs[r * VSTR + c4] = cv;
        }
        __syncthreads();

        // ---- S = Q K^T : warp computes m16 x n32 (4 n8-subtiles) ----
        float s[4][4];
        #pragma unroll
        for (int j = 0; j < 4; ++j)
            #pragma unroll
            for (int c = 0; c < 4; ++c) s[j][c] = 0.f;

        #pragma unroll
        for (int kf = 0; kf < 8; ++kf) {
            #pragma unroll
            for (int j = 0; j < 4; ++j) {
                int key = nbase + j * 8 + g;
                uint32_t b0 = __float_as_uint(Ks[key * KSTR + kf * 8 + qd]);
                uint32_t b1 = __float_as_uint(Ks[key * KSTR + kf * 8 + qd + 4]);
                mma_tf32(s[j][0], s[j][1], s[j][2], s[j][3],
                         qf[kf][0], qf[kf][1], qf[kf][2], qf[kf][3], b0, b1);
            }
        }

        // ---- stream bias inputs (batched for MLP) ----
        size_t base_lo = ((size_t)h * S_LEN + q0 + r_lo) * S_LEN
                         + (size_t)(jt * BN + nbase + 2 * qd);
        size_t base_hi = base_lo + (size_t)8 * S_LEN;

        float2 dlo[4], dhi[4], elo[4], ehi[4];
        int2   mlo[4], mhi[4];
        #pragma unroll
        for (int j = 0; j < 4; ++j) {
            dlo[j] = *(const float2*)(dist + base_lo + j * 8);
            dhi[j] = *(const float2*)(dist + base_hi + j * 8);
        }
        #pragma unroll
        for (int j = 0; j < 4; ++j) {
            elo[j] = *(const float2*)(ener + base_lo + j * 8);
            ehi[j] = *(const float2*)(ener + base_hi + j * 8);
        }
        #pragma unroll
        for (int j = 0; j < 4; ++j) {
            mlo[j] = *(const int2*)(mask + base_lo + j * 8);
            mhi[j] = *(const int2*)(mask + base_hi + j * 8);
        }

        #pragma unroll
        for (int j = 0; j < 4; ++j) {
            float v00 = s[j][0] + lut(tD, dlo[j].x, inv_step) + lut(tE, elo[j].x, inv_step);
            float v01 = s[j][1] + lut(tD, dlo[j].y, inv_step) + lut(tE, elo[j].y, inv_step);
            float v10 = s[j][2] + lut(tD, dhi[j].x, inv_step) + lut(tE, ehi[j].x, inv_step);
            float v11 = s[j][3] + lut(tD, dhi[j].y, inv_step) + lut(tE, ehi[j].y, inv_step);
            s[j][0] = (mlo[j].x == 0) ? -1e9f : v00;
            s[j][1] = (mlo[j].y == 0) ? -1e9f : v01;
            s[j][2] = (mhi[j].x == 0) ? -1e9f : v10;
            s[j][3] = (mhi[j].y == 0) ? -1e9f : v11;
        }

        // ---- online softmax ----
        float pl = -1e30f, ph = -1e30f;
        #pragma unroll
        for (int j = 0; j < 4; ++j) {
            pl = fmaxf(pl, fmaxf(s[j][0], s[j][1]));
            ph = fmaxf(ph, fmaxf(s[j][2], s[j][3]));
        }
        pl = fmaxf(pl, __shfl_xor_sync(0xffffffffu, pl, 1));
        pl = fmaxf(pl, __shfl_xor_sync(0xffffffffu, pl, 2));
        ph = fmaxf(ph, __shfl_xor_sync(0xffffffffu, ph, 1));
        ph = fmaxf(ph, __shfl_xor_sync(0xffffffffu, ph, 2));
        if (qd == 0) {
            Mred[half * 64 + r_lo] = pl;
            Mred[half * 64 + r_hi] = ph;
        }
        __syncthreads();
        float nm_lo = fmaxf(m_lo, fmaxf(Mred[r_lo], Mred[64 + r_lo]));
        float nm_hi = fmaxf(m_hi, fmaxf(Mred[r_hi], Mred[64 + r_hi]));
        float c_lo = __expf(m_lo - nm_lo);
        float c_hi = __expf(m_hi - nm_hi);
        m_lo = nm_lo; m_hi = nm_hi;

        float sl = 0.f, sh = 0.f;
        #pragma unroll
        for (int j = 0; j < 4; ++j) {
            s[j][0] = __expf(s[j][0] - nm_lo); sl += s[j][0];
            s[j][1] = __expf(s[j][1] - nm_lo); sl += s[j][1];
            s[j][2] = __expf(s[j][2] - nm_hi); sh += s[j][2];
            s[j][3] = __expf(s[j][3] - nm_hi); sh += s[j][3];
        }
        sl += __shfl_xor_sync(0xffffffffu, sl, 1);
        sl += __shfl_xor_sync(0xffffffffu, sl, 2);
        sh += __shfl_xor_sync(0xffffffffu, sh, 1);
        sh += __shfl_xor_sync(0xffffffffu, sh, 2);
        l_lo = l_lo * c_lo + sl;
        l_hi = l_hi * c_hi + sh;

        #pragma unroll
        for (int j = 0; j < 8; ++j) {
            o[j][0] *= c_lo; o[j][1] *= c_lo;
            o[j][2] *= c_hi; o[j][3] *= c_hi;
        }

        // ---- O += P V : shfl P (C-layout) into A-layout tf32 fragments ----
        const int kb = half * 32;
        const int l0 = g * 4 + (qd >> 1);
        const int l1 = l0 + 2;
        const bool odd = (qd & 1);
        #pragma unroll
        for (int kf = 0; kf < 4; ++kf) {
            float v0 = __shfl_sync(0xffffffffu, s[kf][0], l0);
            float v1 = __shfl_sync(0xffffffffu, s[kf][1], l0);
            float v2 = __shfl_sync(0xffffffffu, s[kf][2], l0);
            float v3 = __shfl_sync(0xffffffffu, s[kf][3], l0);
            float w0 = __shfl_sync(0xffffffffu, s[kf][0], l1);
            float w1 = __shfl_sync(0xffffffffu, s[kf][1], l1);
            float w2 = __shfl_sync(0xffffffffu, s[kf][2], l1);
            float w3 = __shfl_sync(0xffffffffu, s[kf][3], l1);
            uint32_t a0 = f2tf(odd ? v1 : v0);
            uint32_t a1 = f2tf(odd ? v3 : v2);
            uint32_t a2 = f2tf(odd ? w1 : w0);
            uint32_t a3 = f2tf(odd ? w3 : w2);
            int vr = kb + kf * 8 + qd;
            #pragma unroll
            for (int j = 0; j < 8; ++j) {
                uint32_t b0 = __float_as_uint(Vs[vr * VSTR + j * 8 + g]);
                uint32_t b1 = __float_as_uint(Vs[(vr + 4) * VSTR + j * 8 + g]);
                mma_tf32(o[j][0], o[j][1], o[j][2], o[j][3], a0, a1, a2, a3, b0, b1);
            }
        }
    }

    // ---- epilogue: combine the two key-halves, normalize, store ----
    if (qd == 0) {
        Lred[half * 64 + r_lo] = l_lo;
        Lred[half * 64 + r_hi] = l_hi;
    }
    float* Obuf = Ks;   // reuse (all Ks reads completed before last mid-tile sync)
    if (half == 0) {
        #pragma unroll
        for (int j = 0; j < 8; ++j) {
            *(float2*)&Obuf[r_lo * KSTR + j * 8 + 2 * qd] = make_float2(o[j][0], o[j][1]);
            *(float2*)&Obuf[r_hi * KSTR + j * 8 + 2 * qd] = make_float2(o[j][2], o[j][3]);
        }
    }
    __syncthreads();
    if (half == 1) {
        float il_lo = 1.0f / (Lred[r_lo] + Lred[64 + r_lo]);
        float il_hi = 1.0f / (Lred[r_hi] + Lred[64 + r_hi]);
        float* og = out + ((size_t)h * S_LEN + q0) * DH;
        #pragma unroll
        for (int j = 0; j < 8; ++j) {
            float2 t0 = *(float2*)&Obuf[r_lo * KSTR + j * 8 + 2 * qd];
            float2 t1 = *(float2*)&Obuf[r_hi * KSTR + j * 8 + 2 * qd];
            float2 r0 = make_float2((o[j][0] + t0.x) * il_lo, (o[j][1] + t0.y) * il_lo);
            float2 r1 = make_float2((o[j][2] + t1.x) * il_hi, (o[j][3] + t1.y) * il_hi);
            *(float2*)(og + r_lo * DH + j * 8 + 2 * qd) = r0;
            *(float2*)(og + r_hi * DH + j * 8 + 2 * qd) = r1;
        }
    }
}

// ---------------------------------------------------------------------------
// Launch
// ---------------------------------------------------------------------------
extern "C" void kernel_launch(void* const* d_in, const int* in_sizes, int n_in,
                              void* d_out, int out_size)
{
    const float* Q    = (const float*)d_in[0];
    const float* K    = (const float*)d_in[1];
    const float* V    = (const float*)d_in[2];
    const float* dist = (const float*)d_in[3];
    const float* ener = (const float*)d_in[4];
    const int*   mask = (const int*)  d_in[5];
    const float* muD  = (const float*)d_in[6];
    const float* sgD  = (const float*)d_in[7];
    const float* bD   = (const float*)d_in[8];
    const float* muE  = (const float*)d_in[9];
    const float* sgE  = (const float*)d_in[10];
    const float* bE   = (const float*)d_in[11];
    const float* W1   = (const float*)d_in[12];
    const float* b1   = (const float*)d_in[13];
    const float* W2   = (const float*)d_in[14];
    const float* b2   = (const float*)d_in[15];
    float* out = (float*)d_out;

    int KG = in_sizes[6];
    if (KG > 16) KG = 16;

    build_tables_kernel<<<dim3(NTAB / 256, 2), 256>>>(
        muD, sgD, bD, muE, sgE, bE, W1, b1, W2, b2, KG);

    const int SMEM_BYTES = (64 * KSTR + 64 * VSTR + 256) * (int)sizeof(float)
                         + 2 * NTAB * (int)sizeof(float2);
    cudaFuncSetAttribute(attn_kernel,
                         cudaFuncAttributeMaxDynamicSharedMemorySize, SMEM_BYTES);

    attn_kernel<<<dim3(S_LEN / BM, HEADS), 256, SMEM_BYTES>>>(
        Q, K, V, dist, ener, mask, out);
}